// round 2
// baseline (speedup 1.0000x reference)
#include <cuda_runtime.h>

// InteractionArch: out[b] = concat(dense[b] (128),
//                                  triu(k=1) of Gram(concat(dense[b], sparse[b].reshape(26,128))) (351))
// B=16384, D=128, F=26, OUTW=479.
//
// One warp per sample. Lane owns 4 dims (float4) of all 27 vectors in registers.
// Pairs processed in chunks of 32; a halving-butterfly reduce turns 32 lane-partial
// sums into 32 final dots (one per lane) with 31 shuffles total -> coalesced store.

#define BNUM  16384
#define FF    26
#define NV    27      // 1 dense + 26 sparse
#define OUTW  479     // 128 + 351

__global__ __launch_bounds__(256, 1)
void interact_kernel(const float* __restrict__ dense,
                     const float* __restrict__ sparse,
                     float* __restrict__ out)
{
    const int gw   = (blockIdx.x * blockDim.x + threadIdx.x) >> 5;  // sample id
    const int lane = threadIdx.x & 31;
    if (gw >= BNUM) return;

    const float4* d4 = reinterpret_cast<const float4*>(dense)  + (size_t)gw * 32;
    const float4* s4 = reinterpret_cast<const float4*>(sparse) + (size_t)gw * (FF * 32);

    // Load all 27 vectors, 4 dims per lane (dims lane*4 .. lane*4+3).
    float4 v[NV];
    v[0] = d4[lane];
#pragma unroll
    for (int f = 0; f < FF; ++f)
        v[f + 1] = s4[f * 32 + lane];

    float* ob = out + (size_t)gw * OUTW;

    // Dense passthrough (128 floats). Row base is not 16B-aligned for odd gw,
    // so scalar stores.
    ob[lane * 4 + 0] = v[0].x;
    ob[lane * 4 + 1] = v[0].y;
    ob[lane * 4 + 2] = v[0].z;
    ob[lane * 4 + 3] = v[0].w;

    float p[32];
    int slot  = 0;     // folded to constants by full unroll
    int obase = 128;

#pragma unroll
    for (int f = 0; f < NV; ++f) {
#pragma unroll
        for (int g = f + 1; g < NV; ++g) {
            float s = v[f].x * v[g].x;
            s = fmaf(v[f].y, v[g].y, s);
            s = fmaf(v[f].z, v[g].z, s);
            s = fmaf(v[f].w, v[g].w, s);
            p[slot] = s;
            ++slot;
            if (slot == 32) {
                // Halving butterfly: 31 shuffles reduce 32 sums across the warp;
                // lane j ends holding the full dot for pair (chunk_base + j).
#pragma unroll
                for (int m = 16; m >= 1; m >>= 1) {
#pragma unroll
                    for (int i = 0; i < m; ++i) {
                        const bool up  = (lane & m) != 0;
                        float send = up ? p[i] : p[i + m];
                        float recv = __shfl_xor_sync(0xffffffffu, send, m);
                        float keep = up ? p[i + m] : p[i];
                        p[i] = keep + recv;
                    }
                }
                ob[obase + lane] = p[0];
                obase += 32;
                slot = 0;
            }
        }
    }

    // Tail chunk: 351 - 320 = 31 pairs; pad slot 31 with zero.
    p[31] = 0.0f;
#pragma unroll
    for (int m = 16; m >= 1; m >>= 1) {
#pragma unroll
        for (int i = 0; i < m; ++i) {
            const bool up  = (lane & m) != 0;
            float send = up ? p[i] : p[i + m];
            float recv = __shfl_xor_sync(0xffffffffu, send, m);
            float keep = up ? p[i + m] : p[i];
            p[i] = keep + recv;
        }
    }
    if (lane < 31) ob[obase + lane] = p[0];
}

extern "C" void kernel_launch(void* const* d_in, const int* in_sizes, int n_in,
                              void* d_out, int out_size)
{
    const float* dense  = (const float*)d_in[0];
    const float* sparse = (const float*)d_in[1];
    float* out = (float*)d_out;

    // 16384 samples, 1 warp each, 8 warps/block -> 2048 blocks.
    interact_kernel<<<2048, 256>>>(dense, sparse, out);
}